// round 12
// baseline (speedup 1.0000x reference)
#include <cuda_runtime.h>
#include <cuda_bf16.h>
#include <cstdint>

// Problem constants
#define GM 4608   // 512 * 9 rows on both sides
#define GK 3840   // feature dim

// ---------------- device scratch (static globals: no runtime allocs) ----------------
__device__ __align__(256) __nv_bfloat16 g_A[(size_t)GM * GK];   // query, bf16
__device__ __align__(256) __nv_bfloat16 g_B[(size_t)GM * GK];   // target, bf16
__device__ __align__(256) float g_S[(size_t)GM * GM];           // similarity matrix (85 MB)
__device__ float g_f2f[512 * 512];
__device__ float g_x1[32 * 256 * 256];
__device__ float g_x2[64 * 128 * 128];
__device__ float g_x3[128 * 128 * 128];
__device__ float g_rowmax[128];

// ---------------- fp32 -> bf16 conversion ----------------
__global__ void convert_kernel(const float4* __restrict__ q, const float4* __restrict__ t) {
    const size_t n = (size_t)GM * GK / 4;
    __nv_bfloat162* A2 = (__nv_bfloat162*)g_A;
    __nv_bfloat162* B2 = (__nv_bfloat162*)g_B;
    for (size_t i = (size_t)blockIdx.x * blockDim.x + threadIdx.x; i < n;
         i += (size_t)gridDim.x * blockDim.x) {
        float4 a = q[i];
        float4 b = t[i];
        A2[2 * i]     = __floats2bfloat162_rn(a.x, a.y);
        A2[2 * i + 1] = __floats2bfloat162_rn(a.z, a.w);
        B2[2 * i]     = __floats2bfloat162_rn(b.x, b.y);
        B2[2 * i + 1] = __floats2bfloat162_rn(b.z, b.w);
    }
}

// =================================================================================
// GEMM: S = A @ B^T (bf16 in, fp32 accum), mma.sync multistage pipeline
// CTA tile 128(M) x 128(N) x 64(K), 2-stage smem ring (64 KB), 4 warps (2x2),
// warp tile 64x64, *** 3 CTAs/SM *** -> 444 concurrent CTAs -> 3 waves (97.3% util
// vs 87.6% at 2/SM).  ONE __syncthreads per k-iter; prefetch issued a full
// iteration (~4K cyc) ahead so 1-deep lookahead still hides memory latency.
// =================================================================================
#define BM 128
#define BN 128
#define BK 64
#define STAGES 2
#define NITER (GK / BK)   // 60

#define SA_STAGE (BM * BK * 2)        // 16384 B
#define SB_STAGE (BN * BK * 2)        // 16384 B
#define SB_BASE  (STAGES * SA_STAGE)  // 32768
#define SMEM_TOTAL (SB_BASE + STAGES * SB_STAGE)   // 65536 (64 KB)

__device__ __forceinline__ uint32_t smem_u32(const void* p) {
    return (uint32_t)__cvta_generic_to_shared(p);
}
__device__ __forceinline__ void cp_async16(uint32_t s, const void* g) {
    asm volatile("cp.async.cg.shared.global [%0],[%1],16;\n" ::"r"(s), "l"(g));
}
// SW128-style xor swizzle: permutes 16B units within each 1KB (8-row) block
__device__ __forceinline__ uint32_t sw128(uint32_t off) {
    return off ^ ((off >> 3) & 0x70);
}

__global__ __launch_bounds__(128, 3) void gemm_kernel() {
    extern __shared__ char smem[];
    const uint32_t sbase = smem_u32(smem);

    const int tid  = threadIdx.x;
    const int lane = tid & 31;
    const int wid  = tid >> 5;          // 0..3
    const int m0 = blockIdx.y * BM;
    const int n0 = blockIdx.x * BN;
    const int wm = (wid & 1) * 64;      // 2 warps over M
    const int wn = (wid >> 1) * 64;     // 2 warps over N

    float acc[4][8][4];
#pragma unroll
    for (int i = 0; i < 4; i++)
#pragma unroll
        for (int j = 0; j < 8; j++)
#pragma unroll
            for (int k = 0; k < 4; k++) acc[i][j][k] = 0.f;

    // ---- stage loader: A 1024 + B 1024 16B-chunks over 128 threads ----
    auto load_stage = [&](int slot, int k0) {
        const uint32_t abase = sbase + slot * SA_STAGE;
        const uint32_t bbase = sbase + SB_BASE + slot * SB_STAGE;
#pragma unroll
        for (int i = 0; i < 8; i++) {
            const int c = tid + 128 * i;
            const int row = c >> 3, col = c & 7;
            cp_async16(abase + sw128(row * 128 + col * 16),
                       g_A + (size_t)(m0 + row) * GK + k0 + col * 8);
        }
#pragma unroll
        for (int i = 0; i < 8; i++) {
            const int c = tid + 128 * i;
            const int row = c >> 3, col = c & 7;
            cp_async16(bbase + sw128(row * 128 + col * 16),
                       g_B + (size_t)(n0 + row) * GK + k0 + col * 8);
        }
        asm volatile("cp.async.commit_group;\n" ::);
    };

    // ---- prologue: fill stage 0 ----
    load_stage(0, 0);

    int slot = 0;
    for (int kt = 0; kt < NITER; kt++) {
        // stage kt was committed last iteration (or prologue) -> wait for it
        asm volatile("cp.async.wait_group 0;\n" ::);
        __syncthreads();
        // prefetch stage kt+1 into the other buffer; issued BEFORE compute so the
        // load overlaps this iteration's ~4K-cycle MMA block
        if (kt + 1 < NITER) load_stage(slot ^ 1, (kt + 1) * BK);

        const uint32_t abase = sbase + slot * SA_STAGE;
        const uint32_t bbase = sbase + SB_BASE + slot * SB_STAGE;

#pragma unroll
        for (int ks = 0; ks < 4; ks++) {
            uint32_t a[4][4];
#pragma unroll
            for (int mt = 0; mt < 4; mt++) {
                const int r  = wm + mt * 16 + (lane & 15);
                const int kk = ks * 16 + (lane >> 4) * 8;
                const uint32_t addr = abase + sw128(r * 128 + kk * 2);
                asm volatile("ldmatrix.sync.aligned.m8n8.x4.shared.b16 {%0,%1,%2,%3},[%4];\n"
                             : "=r"(a[mt][0]), "=r"(a[mt][1]), "=r"(a[mt][2]), "=r"(a[mt][3])
                             : "r"(addr));
            }
            uint32_t b[8][2];
#pragma unroll
            for (int np = 0; np < 4; np++) {
                const int r  = wn + np * 16 + (lane >> 4) * 8 + (lane & 7);
                const int kk = ks * 16 + ((lane >> 3) & 1) * 8;
                const uint32_t addr = bbase + sw128(r * 128 + kk * 2);
                asm volatile("ldmatrix.sync.aligned.m8n8.x4.shared.b16 {%0,%1,%2,%3},[%4];\n"
                             : "=r"(b[2 * np][0]), "=r"(b[2 * np][1]),
                               "=r"(b[2 * np + 1][0]), "=r"(b[2 * np + 1][1])
                             : "r"(addr));
            }
#pragma unroll
            for (int mt = 0; mt < 4; mt++)
#pragma unroll
                for (int nt = 0; nt < 8; nt++) {
                    asm volatile(
                        "mma.sync.aligned.m16n8k16.row.col.f32.bf16.bf16.f32 "
                        "{%0,%1,%2,%3},{%4,%5,%6,%7},{%8,%9},{%0,%1,%2,%3};\n"
                        : "+f"(acc[mt][nt][0]), "+f"(acc[mt][nt][1]),
                          "+f"(acc[mt][nt][2]), "+f"(acc[mt][nt][3])
                        : "r"(a[mt][0]), "r"(a[mt][1]), "r"(a[mt][2]), "r"(a[mt][3]),
                          "r"(b[nt][0]), "r"(b[nt][1]));
                }
        }
        slot ^= 1;
    }

    // ---- epilogue: write fp32 tile to g_S ----
#pragma unroll
    for (int mt = 0; mt < 4; mt++) {
        const int r = m0 + wm + mt * 16 + (lane >> 2);
#pragma unroll
        for (int nt = 0; nt < 8; nt++) {
            const int c = n0 + wn + nt * 8 + (lane & 3) * 2;
            float* p0 = g_S + (size_t)r * GM + c;
            p0[0] = acc[mt][nt][0];
            p0[1] = acc[mt][nt][1];
            float* p1 = p0 + (size_t)8 * GM;
            p1[0] = acc[mt][nt][2];
            p1[1] = acc[mt][nt][3];
        }
    }
}

// ---------------- f2f[i][j] = mean_o max_p S[i*9+o][j*9+p] ----------------
__global__ void f2f_kernel() {
    const int idx = blockIdx.x * blockDim.x + threadIdx.x;
    if (idx >= 512 * 512) return;
    const int i = idx >> 9, j = idx & 511;
    float s = 0.f;
#pragma unroll
    for (int o = 0; o < 9; o++) {
        const float* row = g_S + (size_t)(i * 9 + o) * GM + j * 9;
        float m = row[0];
#pragma unroll
        for (int p = 1; p < 9; p++) m = fmaxf(m, row[p]);
        s += m;
    }
    g_f2f[idx] = s * (1.f / 9.f);
}

// ---------------- conv layer 1 (CIN=1): 16 output channels per block --------------
__global__ __launch_bounds__(256) void conv1_kernel(const float* __restrict__ w,
                                                    const float* __restrict__ bias) {
    constexpr int H = 512;
    const float* in = g_f2f;
    float* out = g_x1;

    __shared__ float tile[34][34];
    __shared__ float wsh[16][9];

    const int tid = threadIdx.x;
    const int tx = tid & 15, ty = tid >> 4;
    const int x0 = blockIdx.x * 32, y0 = blockIdx.y * 32;
    const int ocg = blockIdx.z;          // 0..1, 16 ocs each

    for (int idx = tid; idx < 34 * 34; idx += 256) {
        const int r = idx / 34, c = idx - r * 34;
        const int gy = y0 + r - 1, gx = x0 + c - 1;
        float v = 0.f;
        if (gy >= 0 && gy < H && gx >= 0 && gx < H) v = in[(size_t)gy * H + gx];
        (&tile[0][0])[idx] = v;
    }
    if (tid < 144) wsh[tid / 9][tid % 9] = w[(size_t)(ocg * 16 + tid / 9) * 9 + tid % 9];
    __syncthreads();

    float v[4][4];
#pragma unroll
    for (int dy = 0; dy < 4; dy++)
#pragma unroll
        for (int dx = 0; dx < 4; dx++) v[dy][dx] = tile[2 * ty + dy][2 * tx + dx];

#pragma unroll
    for (int oc = 0; oc < 16; oc++) {
        float wr[9];
#pragma unroll
        for (int t2 = 0; t2 < 9; t2++) wr[t2] = wsh[oc][t2];
        float p[4];
#pragma unroll
        for (int py = 0; py < 2; py++)
#pragma unroll
            for (int px = 0; px < 2; px++) {
                float s = 0.f;
#pragma unroll
                for (int kh = 0; kh < 3; kh++)
#pragma unroll
                    for (int kw = 0; kw < 3; kw++)
                        s += v[py + kh][px + kw] * wr[kh * 3 + kw];
                p[py * 2 + px] = s;
            }
        const float b = bias[ocg * 16 + oc];
        float m = fmaxf(fmaxf(p[0], p[1]), fmaxf(p[2], p[3])) + b;
        m = fmaxf(m, 0.f);
        out[(size_t)(ocg * 16 + oc) * 256 * 256 + (size_t)(blockIdx.y * 16 + ty) * 256 +
            (blockIdx.x * 16 + tx)] = m;
    }
}

// ---------------- conv layers 2/3: preloaded weights + double-buffered tile ------
// LAYER 2: 32->64, H=256, pool.  LAYER 3: 64->128, H=128, no pool.
template <int LAYER>
__global__ __launch_bounds__(256) void convN_kernel(const float* __restrict__ w,
                                                    const float* __restrict__ bias) {
    constexpr int CIN  = (LAYER == 2) ? 32 : 64;
    constexpr int H    = (LAYER == 2) ? 256 : 128;
    constexpr bool POOL = (LAYER == 2);
    const float* in = (LAYER == 2) ? g_x1 : g_x2;
    float* out = (LAYER == 2) ? g_x2 : g_x3;

    __shared__ float tile[2][34][34];
    __shared__ float wsh[CIN][8][9];

    const int tid = threadIdx.x;
    const int tx = tid & 15, ty = tid >> 4;
    const int x0 = blockIdx.x * 32, y0 = blockIdx.y * 32;
    const int ocg = blockIdx.z;

    // preload ALL weights for this ocg once
    for (int idx = tid; idx < CIN * 72; idx += 256) {
        const int ic = idx / 72, rem = idx - ic * 72;
        const int oc = rem / 9, k = rem - oc * 9;
        wsh[ic][oc][k] = w[(size_t)((ocg * 8 + oc) * CIN + ic) * 9 + k];
    }

    auto load_tile = [&](int ic, int buf) {
        const float* src = in + (size_t)ic * H * H;
        for (int idx = tid; idx < 34 * 34; idx += 256) {
            const int r = idx / 34, c = idx - r * 34;
            const int gy = y0 + r - 1, gx = x0 + c - 1;
            float v = 0.f;
            if (gy >= 0 && gy < H && gx >= 0 && gx < H) v = src[(size_t)gy * H + gx];
            (&tile[buf][0][0])[idx] = v;
        }
    };

    float acc[8][4] = {};

    load_tile(0, 0);
    __syncthreads();

    for (int ic = 0; ic < CIN; ic++) {
        if (ic + 1 < CIN) load_tile(ic + 1, (ic + 1) & 1);

        const int buf = ic & 1;
        float v[4][4];
#pragma unroll
        for (int dy = 0; dy < 4; dy++)
#pragma unroll
            for (int dx = 0; dx < 4; dx++) v[dy][dx] = tile[buf][2 * ty + dy][2 * tx + dx];

#pragma unroll
        for (int oc = 0; oc < 8; oc++) {
            float wr[9];
#pragma unroll
            for (int t2 = 0; t2 < 9; t2++) wr[t2] = wsh[ic][oc][t2];
#pragma unroll
            for (int py = 0; py < 2; py++)
#pragma unroll
                for (int px = 0; px < 2; px++) {
                    float s = acc[oc][py * 2 + px];
#pragma unroll
                    for (int kh = 0; kh < 3; kh++)
#pragma unroll
                        for (int kw = 0; kw < 3; kw++)
                            s += v[py + kh][px + kw] * wr[kh * 3 + kw];
                    acc[oc][py * 2 + px] = s;
                }
        }
        __syncthreads();
    }

#pragma unroll
    for (int oc = 0; oc < 8; oc++) {
        const float b = bias[ocg * 8 + oc];
        if (POOL) {
            constexpr int Hp = H / 2;
            float m = fmaxf(fmaxf(acc[oc][0], acc[oc][1]), fmaxf(acc[oc][2], acc[oc][3])) + b;
            m = fmaxf(m, 0.f);
            out[(size_t)(ocg * 8 + oc) * Hp * Hp + (size_t)(blockIdx.y * 16 + ty) * Hp +
                (blockIdx.x * 16 + tx)] = m;
        } else {
#pragma unroll
            for (int py = 0; py < 2; py++)
#pragma unroll
                for (int px = 0; px < 2; px++)
                    out[(size_t)(ocg * 8 + oc) * H * H + (size_t)(y0 + 2 * ty + py) * H +
                        (x0 + 2 * tx + px)] = fmaxf(acc[oc][py * 2 + px] + b, 0.f);
        }
    }
}

// ---------------- 1x1 conv + clip + per-row max ----------------
__global__ void final_rowmax_kernel(const float* __restrict__ wf, const float* __restrict__ bf) {
    const int h = blockIdx.x;    // 0..127
    const int w = threadIdx.x;   // 0..127
    float s = bf[0];
#pragma unroll 8
    for (int c = 0; c < 128; c++) s += wf[c] * g_x3[(size_t)c * 128 * 128 + h * 128 + w];
    s = fminf(fmaxf(s, -1.f), 1.f);
    __shared__ float red[128];
    red[w] = s;
    __syncthreads();
    for (int st = 64; st > 0; st >>= 1) {
        if (w < st) red[w] = fmaxf(red[w], red[w + st]);
        __syncthreads();
    }
    if (w == 0) g_rowmax[h] = red[0];
}

__global__ void final_mean_kernel(float* __restrict__ out) {
    const int t = threadIdx.x;   // 0..127
    __shared__ float red[128];
    red[t] = g_rowmax[t];
    __syncthreads();
    for (int st = 64; st > 0; st >>= 1) {
        if (t < st) red[t] += red[t + st];
        __syncthreads();
    }
    if (t == 0) out[0] = red[0] / 128.f;
}

// ---------------- launch ----------------
extern "C" void kernel_launch(void* const* d_in, const int* in_sizes, int n_in,
                              void* d_out, int out_size) {
    const float* q  = (const float*)d_in[0];
    const float* t  = (const float*)d_in[1];
    const float* w1 = (const float*)d_in[2];
    const float* b1 = (const float*)d_in[3];
    const float* w2 = (const float*)d_in[4];
    const float* b2 = (const float*)d_in[5];
    const float* w3 = (const float*)d_in[6];
    const float* b3 = (const float*)d_in[7];
    const float* wf = (const float*)d_in[8];
    const float* bf = (const float*)d_in[9];

    // idempotent, not a stream op (graph-capture safe)
    cudaFuncSetAttribute(gemm_kernel, cudaFuncAttributeMaxDynamicSharedMemorySize, SMEM_TOTAL);

    convert_kernel<<<4096, 256>>>((const float4*)q, (const float4*)t);
    gemm_kernel<<<dim3(GM / BN, GM / BM), 128, SMEM_TOTAL>>>();
    f2f_kernel<<<1024, 256>>>();
    conv1_kernel<<<dim3(16, 16, 2), 256>>>(w1, b1);
    convN_kernel<2><<<dim3(8, 8, 8), 256>>>(w2, b2);
    convN_kernel<3><<<dim3(4, 4, 16), 256>>>(w3, b3);
    final_rowmax_kernel<<<128, 128>>>(wf, bf);
    final_mean_kernel<<<1, 128>>>((float*)d_out);
}

// round 13
// speedup vs baseline: 1.0484x; 1.0484x over previous
#include <cuda_runtime.h>
#include <cuda_bf16.h>
#include <cstdint>

// Problem constants
#define GM 4608   // 512 * 9 rows on both sides
#define GK 3840   // feature dim

// ---------------- device scratch (static globals: no runtime allocs) ----------------
__device__ __align__(256) __nv_bfloat16 g_A[(size_t)GM * GK];   // query, bf16
__device__ __align__(256) __nv_bfloat16 g_B[(size_t)GM * GK];   // target, bf16
__device__ __align__(256) float g_S[(size_t)GM * GM];           // similarity matrix (85 MB)
__device__ float g_f2f[512 * 512];
__device__ float g_x1[32 * 256 * 256];
__device__ float g_x2[64 * 128 * 128];
__device__ float g_x3[128 * 128 * 128];
__device__ float g_rowmax[128];

// ---------------- packed f32x2 helpers (sm_100+ family PTX) ----------------
__device__ __forceinline__ unsigned long long pack2(float lo, float hi) {
    unsigned long long r;
    asm("mov.b64 %0,{%1,%2};" : "=l"(r) : "f"(lo), "f"(hi));
    return r;
}
__device__ __forceinline__ void fma2(unsigned long long& d, unsigned long long a,
                                     unsigned long long b) {
    asm("fma.rn.f32x2 %0,%1,%2,%0;" : "+l"(d) : "l"(a), "l"(b));
}
__device__ __forceinline__ void unpack2(float& lo, float& hi, unsigned long long v) {
    asm("mov.b64 {%0,%1},%2;" : "=f"(lo), "=f"(hi) : "l"(v));
}

// ---------------- fp32 -> bf16 conversion ----------------
__global__ void convert_kernel(const float4* __restrict__ q, const float4* __restrict__ t) {
    const size_t n = (size_t)GM * GK / 4;
    __nv_bfloat162* A2 = (__nv_bfloat162*)g_A;
    __nv_bfloat162* B2 = (__nv_bfloat162*)g_B;
    for (size_t i = (size_t)blockIdx.x * blockDim.x + threadIdx.x; i < n;
         i += (size_t)gridDim.x * blockDim.x) {
        float4 a = q[i];
        float4 b = t[i];
        A2[2 * i]     = __floats2bfloat162_rn(a.x, a.y);
        A2[2 * i + 1] = __floats2bfloat162_rn(a.z, a.w);
        B2[2 * i]     = __floats2bfloat162_rn(b.x, b.y);
        B2[2 * i + 1] = __floats2bfloat162_rn(b.z, b.w);
    }
}

// =================================================================================
// GEMM: S = A @ B^T (bf16 in, fp32 accum), mma.sync multistage pipeline
// CTA tile 128(M) x 128(N) x 64(K), 3-stage smem ring, 4 warps (2x2), warp 64x64,
// 2 CTAs/SM (96 KB smem each), ONE __syncthreads per k-iter.  (Round-10 proven.)
// =================================================================================
#define BM 128
#define BN 128
#define BK 64
#define STAGES 3
#define NITER (GK / BK)   // 60

#define SA_STAGE (BM * BK * 2)        // 16384 B
#define SB_STAGE (BN * BK * 2)        // 16384 B
#define SB_BASE  (STAGES * SA_STAGE)  // 49152
#define SMEM_TOTAL (SB_BASE + STAGES * SB_STAGE)   // 98304 (96 KB)

__device__ __forceinline__ uint32_t smem_u32(const void* p) {
    return (uint32_t)__cvta_generic_to_shared(p);
}
__device__ __forceinline__ void cp_async16(uint32_t s, const void* g) {
    asm volatile("cp.async.cg.shared.global [%0],[%1],16;\n" ::"r"(s), "l"(g));
}
// SW128-style xor swizzle: permutes 16B units within each 1KB (8-row) block
__device__ __forceinline__ uint32_t sw128(uint32_t off) {
    return off ^ ((off >> 3) & 0x70);
}

__global__ __launch_bounds__(128, 2) void gemm_kernel() {
    extern __shared__ char smem[];
    const uint32_t sbase = smem_u32(smem);

    const int tid  = threadIdx.x;
    const int lane = tid & 31;
    const int wid  = tid >> 5;          // 0..3
    const int m0 = blockIdx.y * BM;
    const int n0 = blockIdx.x * BN;
    const int wm = (wid & 1) * 64;      // 2 warps over M
    const int wn = (wid >> 1) * 64;     // 2 warps over N

    float acc[4][8][4];
#pragma unroll
    for (int i = 0; i < 4; i++)
#pragma unroll
        for (int j = 0; j < 8; j++)
#pragma unroll
            for (int k = 0; k < 4; k++) acc[i][j][k] = 0.f;

    // ---- stage loader: A 1024 + B 1024 16B-chunks over 128 threads ----
    auto load_stage = [&](int slot, int k0) {
        const uint32_t abase = sbase + slot * SA_STAGE;
        const uint32_t bbase = sbase + SB_BASE + slot * SB_STAGE;
#pragma unroll
        for (int i = 0; i < 8; i++) {
            const int c = tid + 128 * i;
            const int row = c >> 3, col = c & 7;
            cp_async16(abase + sw128(row * 128 + col * 16),
                       g_A + (size_t)(m0 + row) * GK + k0 + col * 8);
        }
#pragma unroll
        for (int i = 0; i < 8; i++) {
            const int c = tid + 128 * i;
            const int row = c >> 3, col = c & 7;
            cp_async16(bbase + sw128(row * 128 + col * 16),
                       g_B + (size_t)(n0 + row) * GK + k0 + col * 8);
        }
        asm volatile("cp.async.commit_group;\n" ::);
    };

    // ---- prologue: fill STAGES-1 = 2 stages ----
#pragma unroll
    for (int s = 0; s < STAGES - 1; s++) load_stage(s, s * BK);

    int slot = 0;
    for (int kt = 0; kt < NITER; kt++) {
        asm volatile("cp.async.wait_group %0;\n" ::"n"(STAGES - 2));
        __syncthreads();
        if (kt + STAGES - 1 < NITER) {
            load_stage((kt + STAGES - 1) % STAGES, (kt + STAGES - 1) * BK);
        } else {
            asm volatile("cp.async.commit_group;\n" ::);
        }

        const uint32_t abase = sbase + slot * SA_STAGE;
        const uint32_t bbase = sbase + SB_BASE + slot * SB_STAGE;

#pragma unroll
        for (int ks = 0; ks < 4; ks++) {
            uint32_t a[4][4];
#pragma unroll
            for (int mt = 0; mt < 4; mt++) {
                const int r  = wm + mt * 16 + (lane & 15);
                const int kk = ks * 16 + (lane >> 4) * 8;
                const uint32_t addr = abase + sw128(r * 128 + kk * 2);
                asm volatile("ldmatrix.sync.aligned.m8n8.x4.shared.b16 {%0,%1,%2,%3},[%4];\n"
                             : "=r"(a[mt][0]), "=r"(a[mt][1]), "=r"(a[mt][2]), "=r"(a[mt][3])
                             : "r"(addr));
            }
            uint32_t b[8][2];
#pragma unroll
            for (int np = 0; np < 4; np++) {
                const int r  = wn + np * 16 + (lane >> 4) * 8 + (lane & 7);
                const int kk = ks * 16 + ((lane >> 3) & 1) * 8;
                const uint32_t addr = bbase + sw128(r * 128 + kk * 2);
                asm volatile("ldmatrix.sync.aligned.m8n8.x4.shared.b16 {%0,%1,%2,%3},[%4];\n"
                             : "=r"(b[2 * np][0]), "=r"(b[2 * np][1]),
                               "=r"(b[2 * np + 1][0]), "=r"(b[2 * np + 1][1])
                             : "r"(addr));
            }
#pragma unroll
            for (int mt = 0; mt < 4; mt++)
#pragma unroll
                for (int nt = 0; nt < 8; nt++) {
                    asm volatile(
                        "mma.sync.aligned.m16n8k16.row.col.f32.bf16.bf16.f32 "
                        "{%0,%1,%2,%3},{%4,%5,%6,%7},{%8,%9},{%0,%1,%2,%3};\n"
                        : "+f"(acc[mt][nt][0]), "+f"(acc[mt][nt][1]),
                          "+f"(acc[mt][nt][2]), "+f"(acc[mt][nt][3])
                        : "r"(a[mt][0]), "r"(a[mt][1]), "r"(a[mt][2]), "r"(a[mt][3]),
                          "r"(b[nt][0]), "r"(b[nt][1]));
                }
        }
        if (++slot == STAGES) slot = 0;
    }

    // ---- epilogue: write fp32 tile to g_S ----
#pragma unroll
    for (int mt = 0; mt < 4; mt++) {
        const int r = m0 + wm + mt * 16 + (lane >> 2);
#pragma unroll
        for (int nt = 0; nt < 8; nt++) {
            const int c = n0 + wn + nt * 8 + (lane & 3) * 2;
            float* p0 = g_S + (size_t)r * GM + c;
            p0[0] = acc[mt][nt][0];
            p0[1] = acc[mt][nt][1];
            float* p1 = p0 + (size_t)8 * GM;
            p1[0] = acc[mt][nt][2];
            p1[1] = acc[mt][nt][3];
        }
    }
}

// ---------------- f2f[i][j] = mean_o max_p S[i*9+o][j*9+p] ----------------
__global__ void f2f_kernel() {
    const int idx = blockIdx.x * blockDim.x + threadIdx.x;
    if (idx >= 512 * 512) return;
    const int i = idx >> 9, j = idx & 511;
    float s = 0.f;
#pragma unroll
    for (int o = 0; o < 9; o++) {
        const float* row = g_S + (size_t)(i * 9 + o) * GM + j * 9;
        float m = row[0];
#pragma unroll
        for (int p = 1; p < 9; p++) m = fmaxf(m, row[p]);
        s += m;
    }
    g_f2f[idx] = s * (1.f / 9.f);
}

// ---------------- conv layer 1 (CIN=1): 16 output channels per block --------------
__global__ __launch_bounds__(256) void conv1_kernel(const float* __restrict__ w,
                                                    const float* __restrict__ bias) {
    constexpr int H = 512;
    const float* in = g_f2f;
    float* out = g_x1;

    __shared__ float tile[34][34];
    __shared__ float wsh[16][9];

    const int tid = threadIdx.x;
    const int tx = tid & 15, ty = tid >> 4;
    const int x0 = blockIdx.x * 32, y0 = blockIdx.y * 32;
    const int ocg = blockIdx.z;          // 0..1, 16 ocs each

    for (int idx = tid; idx < 34 * 34; idx += 256) {
        const int r = idx / 34, c = idx - r * 34;
        const int gy = y0 + r - 1, gx = x0 + c - 1;
        float v = 0.f;
        if (gy >= 0 && gy < H && gx >= 0 && gx < H) v = in[(size_t)gy * H + gx];
        (&tile[0][0])[idx] = v;
    }
    if (tid < 144) wsh[tid / 9][tid % 9] = w[(size_t)(ocg * 16 + tid / 9) * 9 + tid % 9];
    __syncthreads();

    float v[4][4];
#pragma unroll
    for (int dy = 0; dy < 4; dy++)
#pragma unroll
        for (int dx = 0; dx < 4; dx++) v[dy][dx] = tile[2 * ty + dy][2 * tx + dx];

#pragma unroll
    for (int oc = 0; oc < 16; oc++) {
        float wr[9];
#pragma unroll
        for (int t2 = 0; t2 < 9; t2++) wr[t2] = wsh[oc][t2];
        float p[4];
#pragma unroll
        for (int py = 0; py < 2; py++)
#pragma unroll
            for (int px = 0; px < 2; px++) {
                float s = 0.f;
#pragma unroll
                for (int kh = 0; kh < 3; kh++)
#pragma unroll
                    for (int kw = 0; kw < 3; kw++)
                        s += v[py + kh][px + kw] * wr[kh * 3 + kw];
                p[py * 2 + px] = s;
            }
        const float b = bias[ocg * 16 + oc];
        float m = fmaxf(fmaxf(p[0], p[1]), fmaxf(p[2], p[3])) + b;
        m = fmaxf(m, 0.f);
        out[(size_t)(ocg * 16 + oc) * 256 * 256 + (size_t)(blockIdx.y * 16 + ty) * 256 +
            (blockIdx.x * 16 + tx)] = m;
    }
}

// ---------------- conv layers 2/3: f32x2-packed FMA, preloaded dup weights,
//                  double-buffered input tile ------------------------------------
// LAYER 2: 32->64, H=256, pool.  LAYER 3: 64->128, H=128, no pool.
template <int LAYER>
__global__ __launch_bounds__(256) void convN_kernel(const float* __restrict__ w,
                                                    const float* __restrict__ bias) {
    constexpr int CIN  = (LAYER == 2) ? 32 : 64;
    constexpr int H    = (LAYER == 2) ? 256 : 128;
    constexpr bool POOL = (LAYER == 2);
    const float* in = (LAYER == 2) ? g_x1 : g_x2;
    float* out = (LAYER == 2) ? g_x2 : g_x3;

    __shared__ float tile[2][34][34];
    __shared__ unsigned long long wsh2[CIN][8][9];   // weights duplicated (w,w)

    const int tid = threadIdx.x;
    const int tx = tid & 15, ty = tid >> 4;
    const int x0 = blockIdx.x * 32, y0 = blockIdx.y * 32;
    const int ocg = blockIdx.z;

    // preload ALL weights for this ocg once, duplicated into both f32x2 lanes
    for (int idx = tid; idx < CIN * 72; idx += 256) {
        const int ic = idx / 72, rem = idx - ic * 72;
        const int oc = rem / 9, k = rem - oc * 9;
        const float wv = w[(size_t)((ocg * 8 + oc) * CIN + ic) * 9 + k];
        wsh2[ic][oc][k] = pack2(wv, wv);
    }

    auto load_tile = [&](int ic, int buf) {
        const float* src = in + (size_t)ic * H * H;
        for (int idx = tid; idx < 34 * 34; idx += 256) {
            const int r = idx / 34, c = idx - r * 34;
            const int gy = y0 + r - 1, gx = x0 + c - 1;
            float v = 0.f;
            if (gy >= 0 && gy < H && gx >= 0 && gx < H) v = src[(size_t)gy * H + gx];
            (&tile[buf][0][0])[idx] = v;
        }
    };

    // acc2[oc][py] holds the packed (px0, px1) pair
    unsigned long long acc2[8][2];
#pragma unroll
    for (int oc = 0; oc < 8; oc++) {
        acc2[oc][0] = 0ull;
        acc2[oc][1] = 0ull;
    }

    load_tile(0, 0);
    __syncthreads();

    for (int ic = 0; ic < CIN; ic++) {
        if (ic + 1 < CIN) load_tile(ic + 1, (ic + 1) & 1);

        const int buf = ic & 1;
        float v[4][4];
#pragma unroll
        for (int dy = 0; dy < 4; dy++)
#pragma unroll
            for (int dx = 0; dx < 4; dx++) v[dy][dx] = tile[buf][2 * ty + dy][2 * tx + dx];

        // pack horizontal pairs: vp[dy][kw] = (v[dy][kw], v[dy][kw+1])
        unsigned long long vp[4][3];
#pragma unroll
        for (int dy = 0; dy < 4; dy++)
#pragma unroll
            for (int kw = 0; kw < 3; kw++) vp[dy][kw] = pack2(v[dy][kw], v[dy][kw + 1]);

#pragma unroll
        for (int oc = 0; oc < 8; oc++) {
#pragma unroll
            for (int py = 0; py < 2; py++)
#pragma unroll
                for (int kh = 0; kh < 3; kh++)
#pragma unroll
                    for (int kw = 0; kw < 3; kw++)
                        fma2(acc2[oc][py], vp[py + kh][kw], wsh2[ic][oc][kh * 3 + kw]);
        }
        __syncthreads();
    }

#pragma unroll
    for (int oc = 0; oc < 8; oc++) {
        const float b = bias[ocg * 8 + oc];
        float p00, p01, p10, p11;
        unpack2(p00, p01, acc2[oc][0]);
        unpack2(p10, p11, acc2[oc][1]);
        if (POOL) {
            constexpr int Hp = H / 2;
            float m = fmaxf(fmaxf(p00, p01), fmaxf(p10, p11)) + b;
            m = fmaxf(m, 0.f);
            out[(size_t)(ocg * 8 + oc) * Hp * Hp + (size_t)(blockIdx.y * 16 + ty) * Hp +
                (blockIdx.x * 16 + tx)] = m;
        } else {
            float* o0 = out + (size_t)(ocg * 8 + oc) * H * H + (size_t)(y0 + 2 * ty) * H +
                        (x0 + 2 * tx);
            o0[0] = fmaxf(p00 + b, 0.f);
            o0[1] = fmaxf(p01 + b, 0.f);
            o0[H] = fmaxf(p10 + b, 0.f);
            o0[H + 1] = fmaxf(p11 + b, 0.f);
        }
    }
}

// ---------------- 1x1 conv + clip + per-row max ----------------
__global__ void final_rowmax_kernel(const float* __restrict__ wf, const float* __restrict__ bf) {
    const int h = blockIdx.x;    // 0..127
    const int w = threadIdx.x;   // 0..127
    float s = bf[0];
#pragma unroll 8
    for (int c = 0; c < 128; c++) s += wf[c] * g_x3[(size_t)c * 128 * 128 + h * 128 + w];
    s = fminf(fmaxf(s, -1.f), 1.f);
    __shared__ float red[128];
    red[w] = s;
    __syncthreads();
    for (int st = 64; st > 0; st >>= 1) {
        if (w < st) red[w] = fmaxf(red[w], red[w + st]);
        __syncthreads();
    }
    if (w == 0) g_rowmax[h] = red[0];
}

__global__ void final_mean_kernel(float* __restrict__ out) {
    const int t = threadIdx.x;   // 0..127
    __shared__ float red[128];
    red[t] = g_rowmax[t];
    __syncthreads();
    for (int st = 64; st > 0; st >>= 1) {
        if (t < st) red[t] += red[t + st];
        __syncthreads();
    }
    if (t == 0) out[0] = red[0] / 128.f;
}

// ---------------- launch ----------------
extern "C" void kernel_launch(void* const* d_in, const int* in_sizes, int n_in,
                              void* d_out, int out_size) {
    const float* q  = (const float*)d_in[0];
    const float* t  = (const float*)d_in[1];
    const float* w1 = (const float*)d_in[2];
    const float* b1 = (const float*)d_in[3];
    const float* w2 = (const float*)d_in[4];
    const float* b2 = (const float*)d_in[5];
    const float* w3 = (const float*)d_in[6];
    const float* b3 = (const float*)d_in[7];
    const float* wf = (const float*)d_in[8];
    const float* bf = (const float*)d_in[9];

    // idempotent, not a stream op (graph-capture safe)
    cudaFuncSetAttribute(gemm_kernel, cudaFuncAttributeMaxDynamicSharedMemorySize, SMEM_TOTAL);

    convert_kernel<<<4096, 256>>>((const float4*)q, (const float4*)t);
    gemm_kernel<<<dim3(GM / BN, GM / BM), 128, SMEM_TOTAL>>>();
    f2f_kernel<<<1024, 256>>>();
    conv1_kernel<<<dim3(16, 16, 2), 256>>>(w1, b1);
    convN_kernel<2><<<dim3(8, 8, 8), 256>>>(w2, b2);
    convN_kernel<3><<<dim3(4, 4, 16), 256>>>(w3, b3);
    final_rowmax_kernel<<<128, 128>>>(wf, bf);
    final_mean_kernel<<<1, 128>>>((float*)d_out);
}

// round 14
// speedup vs baseline: 1.1307x; 1.0785x over previous
#include <cuda_runtime.h>
#include <cuda_bf16.h>
#include <cstdint>

// Problem constants
#define GM 4608   // 512 * 9 rows on both sides
#define GK 3840   // feature dim

// ---------------- device scratch (static globals: no runtime allocs) ----------------
__device__ __align__(256) __nv_bfloat16 g_A[(size_t)GM * GK];   // query, bf16
__device__ __align__(256) __nv_bfloat16 g_B[(size_t)GM * GK];   // target, bf16
__device__ __align__(256) float g_S[(size_t)GM * GM];           // similarity matrix (85 MB)
__device__ float g_f2f[512 * 512];
__device__ float g_x1[32 * 256 * 256];
__device__ float g_x2[64 * 128 * 128];
__device__ float g_x3[128 * 128 * 128];
__device__ float g_rowmax[128];

// ---------------- fp32 -> bf16 conversion ----------------
__global__ void convert_kernel(const float4* __restrict__ q, const float4* __restrict__ t) {
    const size_t n = (size_t)GM * GK / 4;
    __nv_bfloat162* A2 = (__nv_bfloat162*)g_A;
    __nv_bfloat162* B2 = (__nv_bfloat162*)g_B;
    for (size_t i = (size_t)blockIdx.x * blockDim.x + threadIdx.x; i < n;
         i += (size_t)gridDim.x * blockDim.x) {
        float4 a = q[i];
        float4 b = t[i];
        A2[2 * i]     = __floats2bfloat162_rn(a.x, a.y);
        A2[2 * i + 1] = __floats2bfloat162_rn(a.z, a.w);
        B2[2 * i]     = __floats2bfloat162_rn(b.x, b.y);
        B2[2 * i + 1] = __floats2bfloat162_rn(b.z, b.w);
    }
}

// =================================================================================
// GEMM: S = A @ B^T (bf16 in, fp32 accum), mma.sync multistage pipeline
// CTA tile 128(M) x 128(N) x 64(K), 3-stage smem ring, 4 warps (2x2), warp 64x64,
// 2 CTAs/SM (96 KB smem each), ONE __syncthreads per k-iter.  (Round-10 proven.)
// =================================================================================
#define BM 128
#define BN 128
#define BK 64
#define STAGES 3
#define NITER (GK / BK)   // 60

#define SA_STAGE (BM * BK * 2)        // 16384 B
#define SB_STAGE (BN * BK * 2)        // 16384 B
#define SB_BASE  (STAGES * SA_STAGE)  // 49152
#define SMEM_TOTAL (SB_BASE + STAGES * SB_STAGE)   // 98304 (96 KB)

__device__ __forceinline__ uint32_t smem_u32(const void* p) {
    return (uint32_t)__cvta_generic_to_shared(p);
}
__device__ __forceinline__ void cp_async16(uint32_t s, const void* g) {
    asm volatile("cp.async.cg.shared.global [%0],[%1],16;\n" ::"r"(s), "l"(g));
}
// SW128-style xor swizzle: permutes 16B units within each 1KB (8-row) block
__device__ __forceinline__ uint32_t sw128(uint32_t off) {
    return off ^ ((off >> 3) & 0x70);
}

__global__ __launch_bounds__(128, 2) void gemm_kernel() {
    extern __shared__ char smem[];
    const uint32_t sbase = smem_u32(smem);

    const int tid  = threadIdx.x;
    const int lane = tid & 31;
    const int wid  = tid >> 5;          // 0..3
    const int m0 = blockIdx.y * BM;
    const int n0 = blockIdx.x * BN;
    const int wm = (wid & 1) * 64;      // 2 warps over M
    const int wn = (wid >> 1) * 64;     // 2 warps over N

    float acc[4][8][4];
#pragma unroll
    for (int i = 0; i < 4; i++)
#pragma unroll
        for (int j = 0; j < 8; j++)
#pragma unroll
            for (int k = 0; k < 4; k++) acc[i][j][k] = 0.f;

    // ---- stage loader: A 1024 + B 1024 16B-chunks over 128 threads ----
    auto load_stage = [&](int slot, int k0) {
        const uint32_t abase = sbase + slot * SA_STAGE;
        const uint32_t bbase = sbase + SB_BASE + slot * SB_STAGE;
#pragma unroll
        for (int i = 0; i < 8; i++) {
            const int c = tid + 128 * i;
            const int row = c >> 3, col = c & 7;
            cp_async16(abase + sw128(row * 128 + col * 16),
                       g_A + (size_t)(m0 + row) * GK + k0 + col * 8);
        }
#pragma unroll
        for (int i = 0; i < 8; i++) {
            const int c = tid + 128 * i;
            const int row = c >> 3, col = c & 7;
            cp_async16(bbase + sw128(row * 128 + col * 16),
                       g_B + (size_t)(n0 + row) * GK + k0 + col * 8);
        }
        asm volatile("cp.async.commit_group;\n" ::);
    };

    // ---- prologue: fill STAGES-1 = 2 stages ----
#pragma unroll
    for (int s = 0; s < STAGES - 1; s++) load_stage(s, s * BK);

    int slot = 0;
    for (int kt = 0; kt < NITER; kt++) {
        asm volatile("cp.async.wait_group %0;\n" ::"n"(STAGES - 2));
        __syncthreads();
        if (kt + STAGES - 1 < NITER) {
            load_stage((kt + STAGES - 1) % STAGES, (kt + STAGES - 1) * BK);
        } else {
            asm volatile("cp.async.commit_group;\n" ::);
        }

        const uint32_t abase = sbase + slot * SA_STAGE;
        const uint32_t bbase = sbase + SB_BASE + slot * SB_STAGE;

#pragma unroll
        for (int ks = 0; ks < 4; ks++) {
            uint32_t a[4][4];
#pragma unroll
            for (int mt = 0; mt < 4; mt++) {
                const int r  = wm + mt * 16 + (lane & 15);
                const int kk = ks * 16 + (lane >> 4) * 8;
                const uint32_t addr = abase + sw128(r * 128 + kk * 2);
                asm volatile("ldmatrix.sync.aligned.m8n8.x4.shared.b16 {%0,%1,%2,%3},[%4];\n"
                             : "=r"(a[mt][0]), "=r"(a[mt][1]), "=r"(a[mt][2]), "=r"(a[mt][3])
                             : "r"(addr));
            }
            uint32_t b[8][2];
#pragma unroll
            for (int np = 0; np < 4; np++) {
                const int r  = wn + np * 16 + (lane >> 4) * 8 + (lane & 7);
                const int kk = ks * 16 + ((lane >> 3) & 1) * 8;
                const uint32_t addr = bbase + sw128(r * 128 + kk * 2);
                asm volatile("ldmatrix.sync.aligned.m8n8.x4.shared.b16 {%0,%1,%2,%3},[%4];\n"
                             : "=r"(b[2 * np][0]), "=r"(b[2 * np][1]),
                               "=r"(b[2 * np + 1][0]), "=r"(b[2 * np + 1][1])
                             : "r"(addr));
            }
#pragma unroll
            for (int mt = 0; mt < 4; mt++)
#pragma unroll
                for (int nt = 0; nt < 8; nt++) {
                    asm volatile(
                        "mma.sync.aligned.m16n8k16.row.col.f32.bf16.bf16.f32 "
                        "{%0,%1,%2,%3},{%4,%5,%6,%7},{%8,%9},{%0,%1,%2,%3};\n"
                        : "+f"(acc[mt][nt][0]), "+f"(acc[mt][nt][1]),
                          "+f"(acc[mt][nt][2]), "+f"(acc[mt][nt][3])
                        : "r"(a[mt][0]), "r"(a[mt][1]), "r"(a[mt][2]), "r"(a[mt][3]),
                          "r"(b[nt][0]), "r"(b[nt][1]));
                }
        }
        if (++slot == STAGES) slot = 0;
    }

    // ---- epilogue: write fp32 tile to g_S ----
#pragma unroll
    for (int mt = 0; mt < 4; mt++) {
        const int r = m0 + wm + mt * 16 + (lane >> 2);
#pragma unroll
        for (int nt = 0; nt < 8; nt++) {
            const int c = n0 + wn + nt * 8 + (lane & 3) * 2;
            float* p0 = g_S + (size_t)r * GM + c;
            p0[0] = acc[mt][nt][0];
            p0[1] = acc[mt][nt][1];
            float* p1 = p0 + (size_t)8 * GM;
            p1[0] = acc[mt][nt][2];
            p1[1] = acc[mt][nt][3];
        }
    }
}

// ---------------- f2f[i][j] = mean_o max_p S[i*9+o][j*9+p] ----------------
__global__ void f2f_kernel() {
    const int idx = blockIdx.x * blockDim.x + threadIdx.x;
    if (idx >= 512 * 512) return;
    const int i = idx >> 9, j = idx & 511;
    float s = 0.f;
#pragma unroll
    for (int o = 0; o < 9; o++) {
        const float* row = g_S + (size_t)(i * 9 + o) * GM + j * 9;
        float m = row[0];
#pragma unroll
        for (int p = 1; p < 9; p++) m = fmaxf(m, row[p]);
        s += m;
    }
    g_f2f[idx] = s * (1.f / 9.f);
}

// ---------------- conv layer 1 (CIN=1): 16 output channels per block --------------
__global__ __launch_bounds__(256) void conv1_kernel(const float* __restrict__ w,
                                                    const float* __restrict__ bias) {
    constexpr int H = 512;
    const float* in = g_f2f;
    float* out = g_x1;

    __shared__ float tile[34][34];
    __shared__ float wsh[16][9];

    const int tid = threadIdx.x;
    const int tx = tid & 15, ty = tid >> 4;
    const int x0 = blockIdx.x * 32, y0 = blockIdx.y * 32;
    const int ocg = blockIdx.z;          // 0..1, 16 ocs each

    for (int idx = tid; idx < 34 * 34; idx += 256) {
        const int r = idx / 34, c = idx - r * 34;
        const int gy = y0 + r - 1, gx = x0 + c - 1;
        float v = 0.f;
        if (gy >= 0 && gy < H && gx >= 0 && gx < H) v = in[(size_t)gy * H + gx];
        (&tile[0][0])[idx] = v;
    }
    if (tid < 144) wsh[tid / 9][tid % 9] = w[(size_t)(ocg * 16 + tid / 9) * 9 + tid % 9];
    __syncthreads();

    float v[4][4];
#pragma unroll
    for (int dy = 0; dy < 4; dy++)
#pragma unroll
        for (int dx = 0; dx < 4; dx++) v[dy][dx] = tile[2 * ty + dy][2 * tx + dx];

#pragma unroll
    for (int oc = 0; oc < 16; oc++) {
        float wr[9];
#pragma unroll
        for (int t2 = 0; t2 < 9; t2++) wr[t2] = wsh[oc][t2];
        float p[4];
#pragma unroll
        for (int py = 0; py < 2; py++)
#pragma unroll
            for (int px = 0; px < 2; px++) {
                float s = 0.f;
#pragma unroll
                for (int kh = 0; kh < 3; kh++)
#pragma unroll
                    for (int kw = 0; kw < 3; kw++)
                        s += v[py + kh][px + kw] * wr[kh * 3 + kw];
                p[py * 2 + px] = s;
            }
        const float b = bias[ocg * 16 + oc];
        float m = fmaxf(fmaxf(p[0], p[1]), fmaxf(p[2], p[3])) + b;
        m = fmaxf(m, 0.f);
        out[(size_t)(ocg * 16 + oc) * 256 * 256 + (size_t)(blockIdx.y * 16 + ty) * 256 +
            (blockIdx.x * 16 + tx)] = m;
    }
}

// ---------------- conv layers 2/3: plain FFMA, preloaded weights,
//                  TWO input channels per barrier (4 tile buffers) ----------------
// LAYER 2: 32->64, H=256, pool.  LAYER 3: 64->128, H=128, no pool.
template <int LAYER>
__global__ __launch_bounds__(256) void convN_kernel(const float* __restrict__ w,
                                                    const float* __restrict__ bias) {
    constexpr int CIN  = (LAYER == 2) ? 32 : 64;
    constexpr int H    = (LAYER == 2) ? 256 : 128;
    constexpr bool POOL = (LAYER == 2);
    constexpr int NPAIR = CIN / 2;
    const float* in = (LAYER == 2) ? g_x1 : g_x2;
    float* out = (LAYER == 2) ? g_x2 : g_x3;

    __shared__ float tile[2][2][34][34];     // [pair-set][channel-in-pair]
    __shared__ float wsh[CIN][8][9];

    const int tid = threadIdx.x;
    const int tx = tid & 15, ty = tid >> 4;
    const int x0 = blockIdx.x * 32, y0 = blockIdx.y * 32;
    const int ocg = blockIdx.z;

    // preload ALL weights for this ocg once
    for (int idx = tid; idx < CIN * 72; idx += 256) {
        const int ic = idx / 72, rem = idx - ic * 72;
        const int oc = rem / 9, k = rem - oc * 9;
        wsh[ic][oc][k] = w[(size_t)((ocg * 8 + oc) * CIN + ic) * 9 + k];
    }

    auto load_pair = [&](int g, int set) {
        // loads channels 2g and 2g+1 into tile[set][0..1]
#pragma unroll
        for (int h = 0; h < 2; h++) {
            const float* src = in + (size_t)(2 * g + h) * H * H;
            for (int idx = tid; idx < 34 * 34; idx += 256) {
                const int r = idx / 34, c = idx - r * 34;
                const int gy = y0 + r - 1, gx = x0 + c - 1;
                float v = 0.f;
                if (gy >= 0 && gy < H && gx >= 0 && gx < H) v = src[(size_t)gy * H + gx];
                (&tile[set][h][0][0])[idx] = v;
            }
        }
    };

    float acc[8][4] = {};

    load_pair(0, 0);
    __syncthreads();

    for (int g = 0; g < NPAIR; g++) {
        // prefetch next pair into the other set (overlaps compute below)
        if (g + 1 < NPAIR) load_pair(g + 1, (g + 1) & 1);

        const int set = g & 1;
#pragma unroll
        for (int h = 0; h < 2; h++) {
            const int ic = 2 * g + h;
            float v[4][4];
#pragma unroll
            for (int dy = 0; dy < 4; dy++)
#pragma unroll
                for (int dx = 0; dx < 4; dx++)
                    v[dy][dx] = tile[set][h][2 * ty + dy][2 * tx + dx];

#pragma unroll
            for (int oc = 0; oc < 8; oc++) {
                float wr[9];
#pragma unroll
                for (int t2 = 0; t2 < 9; t2++) wr[t2] = wsh[ic][oc][t2];
#pragma unroll
                for (int py = 0; py < 2; py++)
#pragma unroll
                    for (int px = 0; px < 2; px++) {
                        float s = acc[oc][py * 2 + px];
#pragma unroll
                        for (int kh = 0; kh < 3; kh++)
#pragma unroll
                            for (int kw = 0; kw < 3; kw++)
                                s += v[py + kh][px + kw] * wr[kh * 3 + kw];
                        acc[oc][py * 2 + px] = s;
                    }
            }
        }
        __syncthreads();   // prefetch writes done; set g&1 free for pair g+2
    }

#pragma unroll
    for (int oc = 0; oc < 8; oc++) {
        const float b = bias[ocg * 8 + oc];
        if (POOL) {
            constexpr int Hp = H / 2;
            float m = fmaxf(fmaxf(acc[oc][0], acc[oc][1]), fmaxf(acc[oc][2], acc[oc][3])) + b;
            m = fmaxf(m, 0.f);
            out[(size_t)(ocg * 8 + oc) * Hp * Hp + (size_t)(blockIdx.y * 16 + ty) * Hp +
                (blockIdx.x * 16 + tx)] = m;
        } else {
            float* o0 = out + (size_t)(ocg * 8 + oc) * H * H + (size_t)(y0 + 2 * ty) * H +
                        (x0 + 2 * tx);
            o0[0] = fmaxf(acc[oc][0] + b, 0.f);
            o0[1] = fmaxf(acc[oc][1] + b, 0.f);
            o0[H] = fmaxf(acc[oc][2] + b, 0.f);
            o0[H + 1] = fmaxf(acc[oc][3] + b, 0.f);
        }
    }
}

// ---------------- 1x1 conv + clip + per-row max ----------------
__global__ void final_rowmax_kernel(const float* __restrict__ wf, const float* __restrict__ bf) {
    const int h = blockIdx.x;    // 0..127
    const int w = threadIdx.x;   // 0..127
    float s = bf[0];
#pragma unroll 8
    for (int c = 0; c < 128; c++) s += wf[c] * g_x3[(size_t)c * 128 * 128 + h * 128 + w];
    s = fminf(fmaxf(s, -1.f), 1.f);
    __shared__ float red[128];
    red[w] = s;
    __syncthreads();
    for (int st = 64; st > 0; st >>= 1) {
        if (w < st) red[w] = fmaxf(red[w], red[w + st]);
        __syncthreads();
    }
    if (w == 0) g_rowmax[h] = red[0];
}

__global__ void final_mean_kernel(float* __restrict__ out) {
    const int t = threadIdx.x;   // 0..127
    __shared__ float red[128];
    red[t] = g_rowmax[t];
    __syncthreads();
    for (int st = 64; st > 0; st >>= 1) {
        if (t < st) red[t] += red[t + st];
        __syncthreads();
    }
    if (t == 0) out[0] = red[0] / 128.f;
}

// ---------------- launch ----------------
extern "C" void kernel_launch(void* const* d_in, const int* in_sizes, int n_in,
                              void* d_out, int out_size) {
    const float* q  = (const float*)d_in[0];
    const float* t  = (const float*)d_in[1];
    const float* w1 = (const float*)d_in[2];
    const float* b1 = (const float*)d_in[3];
    const float* w2 = (const float*)d_in[4];
    const float* b2 = (const float*)d_in[5];
    const float* w3 = (const float*)d_in[6];
    const float* b3 = (const float*)d_in[7];
    const float* wf = (const float*)d_in[8];
    const float* bf = (const float*)d_in[9];

    // idempotent, not a stream op (graph-capture safe)
    cudaFuncSetAttribute(gemm_kernel, cudaFuncAttributeMaxDynamicSharedMemorySize, SMEM_TOTAL);

    convert_kernel<<<4096, 256>>>((const float4*)q, (const float4*)t);
    gemm_kernel<<<dim3(GM / BN, GM / BM), 128, SMEM_TOTAL>>>();
    f2f_kernel<<<1024, 256>>>();
    conv1_kernel<<<dim3(16, 16, 2), 256>>>(w1, b1);
    convN_kernel<2><<<dim3(8, 8, 8), 256>>>(w2, b2);
    convN_kernel<3><<<dim3(4, 4, 16), 256>>>(w3, b3);
    final_rowmax_kernel<<<128, 128>>>(wf, bf);
    final_mean_kernel<<<1, 128>>>((float*)d_out);
}